// round 12
// baseline (speedup 1.0000x reference)
#include <cuda_runtime.h>
#include <cuda_bf16.h>
#include <math.h>
#include <stdint.h>

// ---------------- problem constants ----------------
#define BATCH        256
#define EMBED_DIM    512
#define NUM_CLASSES  100000
#define NUM_SUB      3
#define NROWS        300000
#define SCALE        64.0f
#define COS_M  0.8775825618903728f
#define SIN_M  0.479425538604203f
#define TH_    (-0.8775825618903728f)
#define MM_    0.2397127693021015f

// xavier bound = sqrt(6/(512+300000)) ; INVSW = 127/bound. Any consistent scale
// works (it cancels in cos); clamp below guards mis-estimation.
#define INVSW 28422.34f

// ---------------- GEMM tiling (int8 IMMA m16n8k32) ----------------
#define NT      96             // weight rows per CTA = 32 classes exactly
#define NCTA    3125           // 3125 * 96 = 300000
#define KCH     128            // k elems per chunk (128 B int8 per row)
#define NCHUNK  4

// smem offsets
#define SM_A0   0              // 32768 (A chunk buf0: 256 x 128B int8, SW128)
#define SM_A1   32768
#define SM_B0   65536          // 12288 (B buf0: 96 x 128B int8)
#define SM_B1   77824
#define CM_STRIDE 97           // cm[256][97] int32, aliases [0, 99328)
#define SM_RS   99328          // 96 floats (rnorm)
#define SMEM_REQ 99712

// ---------------- device scratch (no allocation) ----------------
__device__ __align__(16) unsigned char g_embf[NCHUNK * 32768]; // swizzled int8 emb, chunked
__device__ float4 g_enorm4[BATCH * (EMBED_DIM / 4)];
__device__ float  g_escale[BATCH];
__device__ float  g_part[(size_t)NCTA * BATCH];
__device__ float  g_p2[256 * BATCH];
__device__ float  g_labcos[BATCH];

// ---------------- helpers ----------------
__device__ __forceinline__ uint32_t s2u(const void* p) {
    uint32_t a;
    asm("{ .reg .u64 t; cvta.to.shared.u64 t, %1; cvt.u32.u64 %0, t; }" : "=r"(a) : "l"(p));
    return a;
}
#define LDM_X4(r, addr) \
    asm volatile("ldmatrix.sync.aligned.m8n8.x4.shared.b16 {%0,%1,%2,%3}, [%4];" \
        : "=r"((r)[0]), "=r"((r)[1]), "=r"((r)[2]), "=r"((r)[3]) : "r"(addr))

__device__ __forceinline__ void mma16832(int* d, const uint32_t* a, uint32_t b0, uint32_t b1) {
    asm volatile(
        "mma.sync.aligned.m16n8k32.row.col.s32.s8.s8.s32 "
        "{%0,%1,%2,%3}, {%4,%5,%6,%7}, {%8,%9}, {%0,%1,%2,%3};"
        : "+r"(d[0]), "+r"(d[1]), "+r"(d[2]), "+r"(d[3])
        : "r"(a[0]), "r"(a[1]), "r"(a[2]), "r"(a[3]), "r"(b0), "r"(b1));
}
#define CP_ASYNC16(smaddr, gptr) \
    asm volatile("cp.async.ca.shared.global [%0], [%1], 16;" :: "r"(smaddr), "l"(gptr) : "memory")
#define CP_COMMIT()  asm volatile("cp.async.commit_group;" ::: "memory")
#define CP_WAIT0()   asm volatile("cp.async.wait_group 0;" ::: "memory")

__device__ __forceinline__ int q8(float v) {
    float c = fmaxf(fminf(v, 127.0f), -127.0f);
    return __float2int_rn(c);
}

// ---------------- K1: normalize; fp32 out + per-sample-scaled int8 swizzled chunks ----------------
__global__ void k1_normalize(const float* __restrict__ emb) {
    int n = blockIdx.x;
    int t = threadIdx.x;   // 128
    float4 v = ((const float4*)(emb + (size_t)n * EMBED_DIM))[t];
    float ss = v.x * v.x + v.y * v.y + v.z * v.z + v.w * v.w;

    __shared__ float red[128];
    red[t] = ss;
    __syncthreads();
    for (int o = 64; o > 0; o >>= 1) { if (t < o) red[t] += red[t + o]; __syncthreads(); }
    float rn = 1.0f / fmaxf(sqrtf(red[0]), 1e-12f);
    float4 o4 = make_float4(v.x * rn, v.y * rn, v.z * rn, v.w * rn);
    g_enorm4[n * (EMBED_DIM / 4) + t] = o4;

    // per-sample max|e| for int8 scale
    float am = fmaxf(fmaxf(fabsf(o4.x), fabsf(o4.y)), fmaxf(fabsf(o4.z), fabsf(o4.w)));
    __syncthreads();
    red[t] = am;
    __syncthreads();
    for (int o = 64; o > 0; o >>= 1) { if (t < o) red[t] = fmaxf(red[t], red[t + o]); __syncthreads(); }
    float rmax = fmaxf(red[0], 1e-12f);
    if (t == 0) g_escale[n] = rmax * (1.0f / 127.0f);
    float inv = 127.0f / rmax;

    int q0 = q8(o4.x * inv), q1 = q8(o4.y * inv), q2 = q8(o4.z * inv), q3 = q8(o4.w * inv);
    uint32_t p = (uint32_t)(q0 & 255) | ((uint32_t)(q1 & 255) << 8)
               | ((uint32_t)(q2 & 255) << 16) | ((uint32_t)(q3 & 255) << 24);
    int chunk = t >> 5;                                  // bytes 4t -> chunk (4t)/128
    uint32_t boff = (uint32_t)n * 128 + ((4 * t) & 127);
    uint32_t sw = boff ^ ((boff >> 3) & 0x70);
    *(uint32_t*)(g_embf + chunk * 32768 + sw) = p;
}

// ---------------- KL: exact fp32 label cosine ----------------
__global__ void kl_label(const float* __restrict__ weight, const int* __restrict__ labels) {
    int n = blockIdx.x;
    int wid = threadIdx.x >> 5;   // 0..2 (subcenter)
    int lane = threadIdx.x & 31;
    int lab = labels[n];
    if (lab < 0) lab = 0;
    if (lab >= NUM_CLASSES) lab = NUM_CLASSES - 1;

    const float4* er = g_enorm4 + n * (EMBED_DIM / 4);
    const float4* wr = (const float4*)(weight + (size_t)(lab * NUM_SUB + wid) * EMBED_DIM);
    float d = 0.0f, q = 0.0f;
    #pragma unroll
    for (int j = 0; j < 4; j++) {
        float4 e = er[lane + 32 * j];
        float4 w = wr[lane + 32 * j];
        d += e.x * w.x + e.y * w.y + e.z * w.z + e.w * w.w;
        q += w.x * w.x + w.y * w.y + w.z * w.z + w.w * w.w;
    }
    #pragma unroll
    for (int o = 16; o > 0; o >>= 1) {
        d += __shfl_xor_sync(0xFFFFFFFFu, d, o);
        q += __shfl_xor_sync(0xFFFFFFFFu, q, o);
    }
    __shared__ float sc[3];
    if (lane == 0) sc[wid] = d / fmaxf(sqrtf(q), 1e-12f);
    __syncthreads();
    if (threadIdx.x == 0) g_labcos[n] = fmaxf(sc[0], fmaxf(sc[1], sc[2]));
}

// ---------------- K2: pipelined int8 IMMA GEMM + fused epilogue ----------------
// M=256, N=96, K chunks of 128 int8. Double-buffered A (cp.async) + B (reg prefetch).
__global__ void __launch_bounds__(256, 1) k2_imma(const float* __restrict__ weight) {
    extern __shared__ char sm[];
    uint32_t sb = s2u(sm);
    int tid = threadIdx.x;
    int w = tid >> 5;
    int lane = tid & 31;
    float* rsum = (float*)(sm + SM_RS);
    size_t wbase = (size_t)blockIdx.x * NT;

    int acc[2][12][4];
    #pragma unroll
    for (int mt = 0; mt < 2; mt++)
        #pragma unroll
        for (int nt = 0; nt < 12; nt++)
            #pragma unroll
            for (int i = 0; i < 4; i++) acc[mt][nt][i] = 0;

    float rs[12];   // per-warp row sumsq (warp w owns rows w+8i)
    #pragma unroll
    for (int i = 0; i < 12; i++) rs[i] = 0.0f;

    // --- ldmatrix lane address precompute (identical math to bf16 version) ---
    int a_r0 = w * 32 + (lane & 7) + ((lane >> 3) & 1) * 8;
    uint32_t a_hi16 = ((lane >> 4) & 1) * 16;
    uint32_t xrA = (uint32_t)((a_r0 & 7) << 4);
    uint32_t aOff = (uint32_t)a_r0 * 128;
    int b_r0 = (lane & 7) + ((lane >> 4) & 1) * 8;
    uint32_t b_k16 = ((lane >> 3) & 1) * 16;
    uint32_t xrB = (uint32_t)((b_r0 & 7) << 4);
    uint32_t bOff = (uint32_t)b_r0 * 128;

    // --- B prefetch: 12 float4/thread/chunk; row = (tid>>5)+8i, f = tid&31 ---
    float4 breg[12];
    const float4* wp4 = (const float4*)weight + wbase * 128;   // 128 float4 per row
    int brow0 = tid >> 5;
    int bf_ = tid & 31;

    // prologue: B chunk 0 regs, A chunk 0 cp.async
    #pragma unroll
    for (int i = 0; i < 12; i++)
        breg[i] = wp4[(size_t)(brow0 + 8 * i) * 128 + bf_];
    {
        const char* src = (const char*)g_embf + (size_t)tid * 16;
        uint32_t dst = sb + SM_A0 + tid * 16;
        #pragma unroll
        for (int i = 0; i < 8; i++) CP_ASYNC16(dst + i * 4096, src + i * 4096);
        CP_COMMIT();
    }

    for (int kc = 0; kc < NCHUNK; kc++) {
        int buf = kc & 1;
        uint32_t aBase = sb + (buf ? SM_A1 : SM_A0);
        uint32_t bBase = sb + (buf ? SM_B1 : SM_B0);

        CP_WAIT0();
        __syncthreads();   // A[kc] landed; MMA(kc-1) reads complete

        // convert prefetched B regs -> int8 swizzled smem + sumsq
        {
            char* bdst = sm + (buf ? SM_B1 : SM_B0);
            #pragma unroll
            for (int i = 0; i < 12; i++) {
                int row = brow0 + 8 * i;
                float4 v = breg[i];
                int q0 = q8(v.x * INVSW), q1 = q8(v.y * INVSW),
                    q2 = q8(v.z * INVSW), q3 = q8(v.w * INVSW);
                uint32_t p = (uint32_t)(q0 & 255) | ((uint32_t)(q1 & 255) << 8)
                           | ((uint32_t)(q2 & 255) << 16) | ((uint32_t)(q3 & 255) << 24);
                uint32_t kb = (uint32_t)bf_ * 4;
                *(uint32_t*)(bdst + row * 128 + (kb ^ ((row & 7) << 4))) = p;
                float ss = (float)(q0 * q0 + q1 * q1 + q2 * q2 + q3 * q3);
                ss += __shfl_xor_sync(0xFFFFFFFFu, ss, 1);
                ss += __shfl_xor_sync(0xFFFFFFFFu, ss, 2);
                ss += __shfl_xor_sync(0xFFFFFFFFu, ss, 4);
                ss += __shfl_xor_sync(0xFFFFFFFFu, ss, 8);
                ss += __shfl_xor_sync(0xFFFFFFFFu, ss, 16);
                rs[i] += ss;
            }
        }

        // next A chunk
        if (kc < NCHUNK - 1) {
            const char* src = (const char*)g_embf + (size_t)(kc + 1) * 32768 + (size_t)tid * 16;
            uint32_t dst = sb + (buf ? SM_A0 : SM_A1) + tid * 16;
            #pragma unroll
            for (int i = 0; i < 8; i++) CP_ASYNC16(dst + i * 4096, src + i * 4096);
            CP_COMMIT();
        }
        __syncthreads();   // B[kc] visible

        // next B LDGs (land during MMA)
        if (kc < NCHUNK - 1) {
            const float4* wp = wp4 + (kc + 1) * 32;
            #pragma unroll
            for (int i = 0; i < 12; i++)
                breg[i] = wp[(size_t)(brow0 + 8 * i) * 128 + bf_];
        }

        // MMA: 4 k32-steps x (2 m-tiles x 12 n-tiles)
        uint32_t aRow0 = aBase + aOff;
        uint32_t aRow1 = aRow0 + 16 * 128;
        uint32_t bRow0 = bBase + bOff;
        #pragma unroll
        for (int ks = 0; ks < 4; ks++) {
            uint32_t kbA = ((uint32_t)(ks * 32) + a_hi16) ^ xrA;
            uint32_t kbB = ((uint32_t)(ks * 32) + b_k16) ^ xrB;
            uint32_t a0[4], a1[4], bfr[6][4];
            LDM_X4(a0, aRow0 + kbA);
            LDM_X4(a1, aRow1 + kbA);
            #pragma unroll
            for (int g = 0; g < 6; g++) LDM_X4(bfr[g], bRow0 + g * 2048 + kbB);
            #pragma unroll
            for (int nt = 0; nt < 12; nt++) {
                uint32_t b0 = bfr[nt >> 1][(nt & 1) * 2];
                uint32_t b1 = bfr[nt >> 1][(nt & 1) * 2 + 1];
                mma16832(acc[0][nt], a0, b0, b1);
                mma16832(acc[1][nt], a1, b0, b1);
            }
        }
    }
    __syncthreads();   // all ldmatrix reads done before cm overwrites buffers

    // row rnorms: 1/||q_w|| (per-warp private rows, lane 0 writes)
    if (lane == 0) {
        #pragma unroll
        for (int i = 0; i < 12; i++)
            rsum[brow0 + 8 * i] = 1.0f / sqrtf(fmaxf(rs[i], 0.25f));
    }

    // dump int accumulators to cm[256][97]
    int* cm = (int*)sm;
    int mrow = w * 32 + (lane >> 2);
    int mcol = (lane & 3) * 2;
    #pragma unroll
    for (int mt = 0; mt < 2; mt++) {
        #pragma unroll
        for (int nt = 0; nt < 12; nt++) {
            int m = mrow + mt * 16;
            int n = nt * 8 + mcol;
            cm[m * CM_STRIDE + n]           = acc[mt][nt][0];
            cm[m * CM_STRIDE + n + 1]       = acc[mt][nt][1];
            cm[(m + 8) * CM_STRIDE + n]     = acc[mt][nt][2];
            cm[(m + 8) * CM_STRIDE + n + 1] = acc[mt][nt][3];
        }
    }
    __syncthreads();

    // thread tid = sample tid: 32 classes, subcenter-max, exp-sum
    float se = g_escale[tid];
    float psum = 0.0f;
    const int* myrow = cm + tid * CM_STRIDE;
    #pragma unroll 8
    for (int c = 0; c < NT / 3; c++) {
        float c0 = (float)myrow[3 * c + 0] * rsum[3 * c + 0];
        float c1 = (float)myrow[3 * c + 1] * rsum[3 * c + 1];
        float c2 = (float)myrow[3 * c + 2] * rsum[3 * c + 2];
        float m = fmaxf(c0, fmaxf(c1, c2)) * se;
        psum += __expf(fmaf(SCALE, m, -64.0f));
    }
    g_part[(size_t)blockIdx.x * BATCH + tid] = psum;
}

// ---------------- K3a: coalesced partial reduce over CTAs ----------------
__global__ void k3a_reduce() {
    int j = blockIdx.x;   // 256 blocks
    int t = threadIdx.x;  // 256
    float s = 0.0f;
    for (int r = j; r < NCTA; r += 256) s += g_part[(size_t)r * BATCH + t];
    g_p2[j * BATCH + t] = s;
}

// ---------------- K3b: final sum + margin correction + mean ----------------
__global__ void k3b_final(float* __restrict__ out) {
    int tid = threadIdx.x;   // 256, thread = sample
    float tot = 0.0f;
    #pragma unroll 8
    for (int j = 0; j < 256; j++) tot += g_p2[j * BATCH + tid];

    float cl = g_labcos[tid];
    float sine = sqrtf(fminf(fmaxf(1.0f - cl * cl, 0.0f), 1.0f));
    float phi = cl * COS_M - sine * SIN_M;
    phi = (cl > TH_) ? phi : (cl - MM_);
    float t2 = tot - __expf(SCALE * cl - 64.0f) + __expf(SCALE * phi - 64.0f);
    float loss = 64.0f + logf(t2) - SCALE * phi;

    __shared__ float red[256];
    red[tid] = loss;
    __syncthreads();
    for (int o = 128; o > 0; o >>= 1) { if (tid < o) red[tid] += red[tid + o]; __syncthreads(); }
    if (tid == 0) out[0] = red[0] * (1.0f / BATCH);
}

// ---------------- launch ----------------
extern "C" void kernel_launch(void* const* d_in, const int* in_sizes, int n_in,
                              void* d_out, int out_size) {
    const float* emb    = (const float*)d_in[0];
    const int*   labels = (const int*)d_in[1];     // int32 (JAX x64 disabled)
    const float* weight = (const float*)d_in[2];
    float* out = (float*)d_out;

    k1_normalize<<<BATCH, 128>>>(emb);
    kl_label<<<BATCH, 96>>>(weight, labels);

    cudaFuncSetAttribute(k2_imma, cudaFuncAttributeMaxDynamicSharedMemorySize, SMEM_REQ);
    k2_imma<<<NCTA, 256, SMEM_REQ>>>(weight);

    k3a_reduce<<<256, 256>>>();
    k3b_final<<<1, 256>>>(out);
}

// round 13
// speedup vs baseline: 1.2708x; 1.2708x over previous
#include <cuda_runtime.h>
#include <cuda_bf16.h>
#include <math.h>
#include <stdint.h>

// ---------------- problem constants ----------------
#define BATCH        256
#define EMBED_DIM    512
#define NUM_CLASSES  100000
#define NUM_SUB      3
#define NROWS        300000
#define SCALE        64.0f
#define COS_M  0.8775825618903728f
#define SIN_M  0.479425538604203f
#define TH_    (-0.8775825618903728f)
#define MM_    0.2397127693021015f

// ---------------- GEMM tiling ----------------
#define NT      96             // weight rows per tile = 32 classes exactly
#define NTILE   3125           // 3125 * 96 = 300000
#define GRIDP   148            // persistent CTAs
#define KCH     64             // k elems per chunk (128 B bf16 per row)
#define NCHUNK  8

// smem offsets (no aliasing: prefetch never overlaps cm)
#define SM_A0   0              // 32768
#define SM_A1   32768          // 32768
#define SM_B0   65536          // 12288
#define SM_B1   77824          // 12288
#define SM_CM   90112          // cm[256][97] floats = 99328
#define CM_STRIDE 97
#define SM_RS   189440         // 96 floats (sumsq accum)
#define SM_RN   189824         // 96 floats (rnorm)
#define SMEM_REQ 190208

// ---------------- device scratch (no allocation) ----------------
__device__ __align__(16) unsigned char g_embf[NCHUNK * 32768]; // swizzled bf16 emb, chunked
__device__ float4 g_enorm4[BATCH * (EMBED_DIM / 4)];
__device__ float  g_part[(size_t)NTILE * BATCH];
__device__ float  g_p2[256 * BATCH];
__device__ float  g_labcos[BATCH];

// ---------------- helpers ----------------
__device__ __forceinline__ uint32_t s2u(const void* p) {
    uint32_t a;
    asm("{ .reg .u64 t; cvta.to.shared.u64 t, %1; cvt.u32.u64 %0, t; }" : "=r"(a) : "l"(p));
    return a;
}
#define LDM_X4(r, addr) \
    asm volatile("ldmatrix.sync.aligned.m8n8.x4.shared.b16 {%0,%1,%2,%3}, [%4];" \
        : "=r"((r)[0]), "=r"((r)[1]), "=r"((r)[2]), "=r"((r)[3]) : "r"(addr))

__device__ __forceinline__ void mma16816(float* d, const uint32_t* a, uint32_t b0, uint32_t b1) {
    asm volatile(
        "mma.sync.aligned.m16n8k16.row.col.f32.bf16.bf16.f32 "
        "{%0,%1,%2,%3}, {%4,%5,%6,%7}, {%8,%9}, {%0,%1,%2,%3};"
        : "+f"(d[0]), "+f"(d[1]), "+f"(d[2]), "+f"(d[3])
        : "r"(a[0]), "r"(a[1]), "r"(a[2]), "r"(a[3]), "r"(b0), "r"(b1));
}
#define CP_ASYNC16(smaddr, gptr) \
    asm volatile("cp.async.ca.shared.global [%0], [%1], 16;" :: "r"(smaddr), "l"(gptr) : "memory")
#define CP_COMMIT()  asm volatile("cp.async.commit_group;" ::: "memory")
#define CP_WAIT0()   asm volatile("cp.async.wait_group 0;" ::: "memory")

// ---------------- K1: normalize; write fp32 + swizzled bf16 chunked layout ----------------
__global__ void k1_normalize(const float* __restrict__ emb) {
    int n = blockIdx.x;
    int t = threadIdx.x;   // 128
    float4 v = ((const float4*)(emb + (size_t)n * EMBED_DIM))[t];
    float ss = v.x * v.x + v.y * v.y + v.z * v.z + v.w * v.w;

    __shared__ float red[128];
    red[t] = ss;
    __syncthreads();
    for (int o = 64; o > 0; o >>= 1) { if (t < o) red[t] += red[t + o]; __syncthreads(); }
    float rn = 1.0f / fmaxf(sqrtf(red[0]), 1e-12f);

    float4 o4 = make_float4(v.x * rn, v.y * rn, v.z * rn, v.w * rn);
    g_enorm4[n * (EMBED_DIM / 4) + t] = o4;

    __nv_bfloat162 p0 = __floats2bfloat162_rn(o4.x, o4.y);
    __nv_bfloat162 p1 = __floats2bfloat162_rn(o4.z, o4.w);
    uint2 u;
    u.x = *(uint32_t*)&p0;
    u.y = *(uint32_t*)&p1;
    int chunk = t >> 4;
    uint32_t boff = (uint32_t)n * 128 + (t & 15) * 8;
    uint32_t sw = boff ^ ((boff >> 3) & 0x70);
    *(uint2*)(g_embf + chunk * 32768 + sw) = u;
}

// ---------------- KL: exact fp32 label cosine ----------------
__global__ void kl_label(const float* __restrict__ weight, const int* __restrict__ labels) {
    int n = blockIdx.x;
    int wid = threadIdx.x >> 5;   // 0..2 (subcenter)
    int lane = threadIdx.x & 31;
    int lab = labels[n];
    if (lab < 0) lab = 0;
    if (lab >= NUM_CLASSES) lab = NUM_CLASSES - 1;

    const float4* er = g_enorm4 + n * (EMBED_DIM / 4);
    const float4* wr = (const float4*)(weight + (size_t)(lab * NUM_SUB + wid) * EMBED_DIM);
    float d = 0.0f, q = 0.0f;
    #pragma unroll
    for (int j = 0; j < 4; j++) {
        float4 e = er[lane + 32 * j];
        float4 w = wr[lane + 32 * j];
        d += e.x * w.x + e.y * w.y + e.z * w.z + e.w * w.w;
        q += w.x * w.x + w.y * w.y + w.z * w.z + w.w * w.w;
    }
    #pragma unroll
    for (int o = 16; o > 0; o >>= 1) {
        d += __shfl_xor_sync(0xFFFFFFFFu, d, o);
        q += __shfl_xor_sync(0xFFFFFFFFu, q, o);
    }
    __shared__ float sc[3];
    if (lane == 0) sc[wid] = d / fmaxf(sqrtf(q), 1e-12f);
    __syncthreads();
    if (threadIdx.x == 0) g_labcos[n] = fmaxf(sc[0], fmaxf(sc[1], sc[2]));
}

// ---------------- K2: persistent pipelined bf16 HMMA GEMM + fused epilogue ----------------
// grid=148 persistent CTAs; tile loop bid, bid+148, ... Each tile: M=256, N=96, K=512
// in 8 chunks of 64, double-buffered A (cp.async) + B (reg prefetch). Next tile's
// chunk-0 loads are issued before the epilogue so the inter-tile latency is hidden.
__global__ void __launch_bounds__(256, 1) k2_hmma(const float* __restrict__ weight) {
    extern __shared__ char sm[];
    uint32_t sb = s2u(sm);
    int tid = threadIdx.x;
    int w = tid >> 5;
    int lane = tid & 31;
    float* rsum = (float*)(sm + SM_RS);
    float* rn   = (float*)(sm + SM_RN);

    // --- ldmatrix lane address precompute ---
    int a_r0 = w * 32 + (lane & 7) + ((lane >> 3) & 1) * 8;
    uint32_t a_hi16 = ((lane >> 4) & 1) * 16;
    uint32_t xrA = (uint32_t)((a_r0 & 7) << 4);
    uint32_t aOff = (uint32_t)a_r0 * 128;
    int b_r0 = (lane & 7) + ((lane >> 4) & 1) * 8;
    uint32_t b_k16 = ((lane >> 3) & 1) * 16;
    uint32_t xrB = (uint32_t)((b_r0 & 7) << 4);
    uint32_t bOff = (uint32_t)b_r0 * 128;

    float4 breg[6];

    // ---- prologue for first tile ----
    int tile = blockIdx.x;
    {
        const float4* wptr = (const float4*)(weight + (size_t)tile * NT * EMBED_DIM);
        #pragma unroll
        for (int i = 0; i < 6; i++) {
            int idx = tid + 256 * i;
            breg[i] = wptr[(size_t)(idx >> 4) * 128 + (idx & 15)];
        }
        const char* src = (const char*)g_embf + (size_t)tid * 16;
        uint32_t dst = sb + SM_A0 + tid * 16;
        #pragma unroll
        for (int i = 0; i < 8; i++) CP_ASYNC16(dst + i * 4096, src + i * 4096);
        CP_COMMIT();
    }

    for (; tile < NTILE; tile += GRIDP) {
        size_t wbase = (size_t)tile * NT;
        int ntile = tile + GRIDP;
        bool have_next = (ntile < NTILE);

        float acc[2][12][4];
        #pragma unroll
        for (int mt = 0; mt < 2; mt++)
            #pragma unroll
            for (int nt = 0; nt < 12; nt++)
                #pragma unroll
                for (int i = 0; i < 4; i++) acc[mt][nt][i] = 0.0f;

        if (tid < NT) rsum[tid] = 0.0f;

        for (int kc = 0; kc < NCHUNK; kc++) {
            int buf = kc & 1;
            uint32_t aBase = sb + (buf ? SM_A1 : SM_A0);
            uint32_t bBase = sb + (buf ? SM_B1 : SM_B0);

            CP_WAIT0();
            __syncthreads();   // A[kc] landed; rsum reset visible (kc==0)

            // convert prefetched B regs -> smem (swizzled) + sumsq
            {
                char* bdst = sm + (buf ? SM_B1 : SM_B0);
                #pragma unroll
                for (int i = 0; i < 6; i++) {
                    int idx = tid + 256 * i;
                    int row = idx >> 4;
                    int f = idx & 15;
                    float4 v = breg[i];
                    float ss = v.x * v.x + v.y * v.y + v.z * v.z + v.w * v.w;
                    __nv_bfloat162 p0 = __floats2bfloat162_rn(v.x, v.y);
                    __nv_bfloat162 p1 = __floats2bfloat162_rn(v.z, v.w);
                    uint2 u;
                    u.x = *(uint32_t*)&p0;
                    u.y = *(uint32_t*)&p1;
                    uint32_t kb = (uint32_t)f * 8;
                    *(uint2*)(bdst + row * 128 + (kb ^ ((row & 7) << 4))) = u;
                    ss += __shfl_xor_sync(0xFFFFFFFFu, ss, 1);
                    ss += __shfl_xor_sync(0xFFFFFFFFu, ss, 2);
                    ss += __shfl_xor_sync(0xFFFFFFFFu, ss, 4);
                    ss += __shfl_xor_sync(0xFFFFFFFFu, ss, 8);
                    if ((tid & 15) == 0) rsum[row] += ss;
                }
            }

            // issue next A chunk (next chunk of this tile, or chunk 0 of next tile)
            if (kc < NCHUNK - 1) {
                const char* src = (const char*)g_embf + (size_t)(kc + 1) * 32768 + (size_t)tid * 16;
                uint32_t dst = sb + (buf ? SM_A0 : SM_A1) + tid * 16;
                #pragma unroll
                for (int i = 0; i < 8; i++) CP_ASYNC16(dst + i * 4096, src + i * 4096);
                CP_COMMIT();
            } else if (have_next) {
                // kc==7 used A1; chunk 0 of next tile goes to A0 (correct parity)
                const char* src = (const char*)g_embf + (size_t)tid * 16;
                uint32_t dst = sb + SM_A0 + tid * 16;
                #pragma unroll
                for (int i = 0; i < 8; i++) CP_ASYNC16(dst + i * 4096, src + i * 4096);
                CP_COMMIT();
            }
            __syncthreads();   // B[kc] smem visible

            // issue next B LDGs (land during MMA)
            if (kc < NCHUNK - 1) {
                const float4* wp = (const float4*)(weight + wbase * EMBED_DIM + (kc + 1) * KCH);
                #pragma unroll
                for (int i = 0; i < 6; i++) {
                    int idx = tid + 256 * i;
                    breg[i] = wp[(size_t)(idx >> 4) * 128 + (idx & 15)];
                }
            } else if (have_next) {
                const float4* wp = (const float4*)(weight + (size_t)ntile * NT * EMBED_DIM);
                #pragma unroll
                for (int i = 0; i < 6; i++) {
                    int idx = tid + 256 * i;
                    breg[i] = wp[(size_t)(idx >> 4) * 128 + (idx & 15)];
                }
            }

            // MMA: 4 k-steps x (2 m-tiles x 12 n-tiles)
            uint32_t aRow0 = aBase + aOff;
            uint32_t aRow1 = aRow0 + 16 * 128;
            uint32_t bRow0 = bBase + bOff;
            #pragma unroll
            for (int ks = 0; ks < 4; ks++) {
                uint32_t kbA = ((uint32_t)(ks * 32) + a_hi16) ^ xrA;
                uint32_t kbB = ((uint32_t)(ks * 32) + b_k16) ^ xrB;
                uint32_t a0[4], a1[4], bfr[6][4];
                LDM_X4(a0, aRow0 + kbA);
                LDM_X4(a1, aRow1 + kbA);
                #pragma unroll
                for (int g = 0; g < 6; g++) LDM_X4(bfr[g], bRow0 + g * 2048 + kbB);
                #pragma unroll
                for (int nt = 0; nt < 12; nt++) {
                    uint32_t b0 = bfr[nt >> 1][(nt & 1) * 2];
                    uint32_t b1 = bfr[nt >> 1][(nt & 1) * 2 + 1];
                    mma16816(acc[0][nt], a0, b0, b1);
                    mma16816(acc[1][nt], a1, b0, b1);
                }
            }
        }

        // ---- epilogue (cm/rn are private regions; next-tile prefetch in flight) ----
        // rsum complete as of chunk 7's second __syncthreads
        if (tid < NT) rn[tid] = 1.0f / fmaxf(sqrtf(rsum[tid]), 1e-12f);

        float* cm = (float*)(sm + SM_CM);
        int mrow = w * 32 + (lane >> 2);
        int mcol = (lane & 3) * 2;
        #pragma unroll
        for (int mt = 0; mt < 2; mt++) {
            #pragma unroll
            for (int nt = 0; nt < 12; nt++) {
                int m = mrow + mt * 16;
                int n = nt * 8 + mcol;
                cm[m * CM_STRIDE + n]           = acc[mt][nt][0];
                cm[m * CM_STRIDE + n + 1]       = acc[mt][nt][1];
                cm[(m + 8) * CM_STRIDE + n]     = acc[mt][nt][2];
                cm[(m + 8) * CM_STRIDE + n + 1] = acc[mt][nt][3];
            }
        }
        __syncthreads();   // cm + rn visible

        float psum = 0.0f;
        const float* myrow = cm + tid * CM_STRIDE;
        #pragma unroll 8
        for (int c = 0; c < NT / 3; c++) {
            float c0 = myrow[3 * c + 0] * rn[3 * c + 0];
            float c1 = myrow[3 * c + 1] * rn[3 * c + 1];
            float c2 = myrow[3 * c + 2] * rn[3 * c + 2];
            float m = fmaxf(c0, fmaxf(c1, c2));
            psum += __expf(SCALE * m - 64.0f);
        }
        g_part[(size_t)tile * BATCH + tid] = psum;
        __syncthreads();   // cm reads done before next tile's epilogue rewrites (and rsum reset)
    }
}

// ---------------- K3a: coalesced partial reduce over tiles ----------------
__global__ void k3a_reduce() {
    int j = blockIdx.x;   // 256 blocks
    int t = threadIdx.x;  // 256
    float s = 0.0f;
    for (int r = j; r < NTILE; r += 256) s += g_part[(size_t)r * BATCH + t];
    g_p2[j * BATCH + t] = s;
}

// ---------------- K3b: final sum + margin correction + mean ----------------
__global__ void k3b_final(float* __restrict__ out) {
    int tid = threadIdx.x;   // 256, thread = sample
    float tot = 0.0f;
    #pragma unroll 8
    for (int j = 0; j < 256; j++) tot += g_p2[j * BATCH + tid];

    float cl = g_labcos[tid];
    float sine = sqrtf(fminf(fmaxf(1.0f - cl * cl, 0.0f), 1.0f));
    float phi = cl * COS_M - sine * SIN_M;
    phi = (cl > TH_) ? phi : (cl - MM_);
    float t2 = tot - __expf(SCALE * cl - 64.0f) + __expf(SCALE * phi - 64.0f);
    float loss = 64.0f + logf(t2) - SCALE * phi;

    __shared__ float red[256];
    red[tid] = loss;
    __syncthreads();
    for (int o = 128; o > 0; o >>= 1) { if (tid < o) red[tid] += red[tid + o]; __syncthreads(); }
    if (tid == 0) out[0] = red[0] * (1.0f / BATCH);
}

// ---------------- launch ----------------
extern "C" void kernel_launch(void* const* d_in, const int* in_sizes, int n_in,
                              void* d_out, int out_size) {
    const float* emb    = (const float*)d_in[0];
    const int*   labels = (const int*)d_in[1];     // int32 (JAX x64 disabled)
    const float* weight = (const float*)d_in[2];
    float* out = (float*)d_out;

    k1_normalize<<<BATCH, 128>>>(emb);
    kl_label<<<BATCH, 96>>>(weight, labels);

    cudaFuncSetAttribute(k2_hmma, cudaFuncAttributeMaxDynamicSharedMemorySize, SMEM_REQ);
    k2_hmma<<<GRIDP, 256, SMEM_REQ>>>(weight);

    k3a_reduce<<<256, 256>>>();
    k3b_final<<<1, 256>>>(out);
}

// round 15
// speedup vs baseline: 2.1195x; 1.6678x over previous
#include <cuda_runtime.h>
#include <cuda_bf16.h>
#include <math.h>
#include <stdint.h>

// ---------------- problem constants ----------------
#define BATCH        256
#define EMBED_DIM    512
#define NUM_CLASSES  100000
#define NUM_SUB      3
#define NROWS        300000
#define SCALE        64.0f
#define COS_M  0.8775825618903728f
#define SIN_M  0.479425538604203f
#define TH_    (-0.8775825618903728f)
#define MM_    0.2397127693021015f

// ---------------- GEMM tiling (R11 configuration) ----------------
#define NT      96             // weight rows per CTA = 32 classes exactly
#define NCTA    3125           // 3125 * 96 = 300000
#define KCH     64             // k elems per chunk (128 B bf16 per row)
#define NCHUNK  8

// smem offsets
#define SM_A0   0              // 32768 (A chunk buf0, SW128 bf16)
#define SM_A1   32768          // 32768 (A chunk buf1)
#define SM_B0   65536          // 12288 (B buf0: 96 x 128B)
#define SM_B1   77824          // 12288 (B buf1)
#define CM_STRIDE 97           // cm[256][97] floats, aliases [0, 99328)
#define SM_RS   99328          // 96 floats
#define SMEM_REQ 99840

#define SUMSTR  32             // g_sums stride (128B -> distinct L2 lines per sample)

// ---------------- device scratch (no allocation) ----------------
__device__ __align__(16) unsigned char g_embf[NCHUNK * 32768]; // swizzled bf16 emb, chunked
__device__ float  g_sums[BATCH * SUMSTR];                      // padded atomic accumulators
__device__ float  g_labcos[BATCH];

// ---------------- helpers ----------------
__device__ __forceinline__ uint32_t s2u(const void* p) {
    uint32_t a;
    asm("{ .reg .u64 t; cvta.to.shared.u64 t, %1; cvt.u32.u64 %0, t; }" : "=r"(a) : "l"(p));
    return a;
}
#define LDM_X4(r, addr) \
    asm volatile("ldmatrix.sync.aligned.m8n8.x4.shared.b16 {%0,%1,%2,%3}, [%4];" \
        : "=r"((r)[0]), "=r"((r)[1]), "=r"((r)[2]), "=r"((r)[3]) : "r"(addr))

__device__ __forceinline__ void mma16816(float* d, const uint32_t* a, uint32_t b0, uint32_t b1) {
    asm volatile(
        "mma.sync.aligned.m16n8k16.row.col.f32.bf16.bf16.f32 "
        "{%0,%1,%2,%3}, {%4,%5,%6,%7}, {%8,%9}, {%0,%1,%2,%3};"
        : "+f"(d[0]), "+f"(d[1]), "+f"(d[2]), "+f"(d[3])
        : "r"(a[0]), "r"(a[1]), "r"(a[2]), "r"(a[3]), "r"(b0), "r"(b1));
}
#define CP_ASYNC16(smaddr, gptr) \
    asm volatile("cp.async.ca.shared.global [%0], [%1], 16;" :: "r"(smaddr), "l"(gptr) : "memory")
#define CP_COMMIT()  asm volatile("cp.async.commit_group;" ::: "memory")
#define CP_WAIT0()   asm volatile("cp.async.wait_group 0;" ::: "memory")

// ---------------- K1: normalize + swizzled bf16 store + fused label cosine ----------------
// grid=BATCH, block=128. Also zeroes this sample's atomic accumulator slot.
__global__ void k1_norm_label(const float* __restrict__ emb,
                              const float* __restrict__ weight,
                              const int* __restrict__ labels) {
    int n = blockIdx.x;
    int t = threadIdx.x;   // 128
    __shared__ float e_s[EMBED_DIM];
    __shared__ float red[128];
    __shared__ float sc[3];

    float4 v = ((const float4*)(emb + (size_t)n * EMBED_DIM))[t];
    float ss = v.x * v.x + v.y * v.y + v.z * v.z + v.w * v.w;
    red[t] = ss;
    __syncthreads();
    for (int o = 64; o > 0; o >>= 1) { if (t < o) red[t] += red[t + o]; __syncthreads(); }
    float rn = 1.0f / fmaxf(sqrtf(red[0]), 1e-12f);

    float4 o4 = make_float4(v.x * rn, v.y * rn, v.z * rn, v.w * rn);
    ((float4*)e_s)[t] = o4;

    // bf16 + SW128-swizzled chunked store for the GEMM A operand
    __nv_bfloat162 p0 = __floats2bfloat162_rn(o4.x, o4.y);
    __nv_bfloat162 p1 = __floats2bfloat162_rn(o4.z, o4.w);
    uint2 u;
    u.x = *(uint32_t*)&p0;
    u.y = *(uint32_t*)&p1;
    int chunk = t >> 4;
    uint32_t boff = (uint32_t)n * 128 + (t & 15) * 8;
    uint32_t sw = boff ^ ((boff >> 3) & 0x70);
    *(uint2*)(g_embf + chunk * 32768 + sw) = u;

    if (t == 0) g_sums[n * SUMSTR] = 0.0f;   // reset atomic accumulator (pre-k2, in-stream)
    __syncthreads();

    // fused label cosine: warp wid (0..2) handles subcenter wid, exact fp32
    int wid = t >> 5;
    int lane = t & 31;
    if (wid < 3) {
        int lab = labels[n];
        if (lab < 0) lab = 0;
        if (lab >= NUM_CLASSES) lab = NUM_CLASSES - 1;
        const float4* wr = (const float4*)(weight + (size_t)(lab * NUM_SUB + wid) * EMBED_DIM);
        float d = 0.0f, q = 0.0f;
        #pragma unroll
        for (int j = 0; j < 4; j++) {
            float4 e = ((const float4*)e_s)[lane + 32 * j];
            float4 w = wr[lane + 32 * j];
            d += e.x * w.x + e.y * w.y + e.z * w.z + e.w * w.w;
            q += w.x * w.x + w.y * w.y + w.z * w.z + w.w * w.w;
        }
        #pragma unroll
        for (int o = 16; o > 0; o >>= 1) {
            d += __shfl_xor_sync(0xFFFFFFFFu, d, o);
            q += __shfl_xor_sync(0xFFFFFFFFu, q, o);
        }
        if (lane == 0) sc[wid] = d / fmaxf(sqrtf(q), 1e-12f);
    }
    __syncthreads();
    if (t == 0) g_labcos[n] = fmaxf(sc[0], fmaxf(sc[1], sc[2]));
}

// ---------------- K2: pipelined bf16 HMMA GEMM + fused epilogue (R11 core) ----------------
// M=256 (warp w -> samples w*32..), N=96, K chunks of 64, double-buffered A (cp.async)
// and B (register prefetch -> convert), 2 syncs/chunk, next-chunk loads overlap MMA.
__global__ void __launch_bounds__(256, 1) k2_hmma(const float* __restrict__ weight) {
    extern __shared__ char sm[];
    uint32_t sb = s2u(sm);
    int tid = threadIdx.x;
    int w = tid >> 5;
    int lane = tid & 31;
    float* rsum = (float*)(sm + SM_RS);
    size_t wbase = (size_t)blockIdx.x * NT;

    if (tid < NT) rsum[tid] = 0.0f;

    float acc[2][12][4];
    #pragma unroll
    for (int mt = 0; mt < 2; mt++)
        #pragma unroll
        for (int nt = 0; nt < 12; nt++)
            #pragma unroll
            for (int i = 0; i < 4; i++) acc[mt][nt][i] = 0.0f;

    // --- ldmatrix lane address precompute ---
    int a_r0 = w * 32 + (lane & 7) + ((lane >> 3) & 1) * 8;
    uint32_t a_hi16 = ((lane >> 4) & 1) * 16;
    uint32_t xrA = (uint32_t)((a_r0 & 7) << 4);
    uint32_t aOff = (uint32_t)a_r0 * 128;
    int b_r0 = (lane & 7) + ((lane >> 4) & 1) * 8;
    uint32_t b_k16 = ((lane >> 3) & 1) * 16;
    uint32_t xrB = (uint32_t)((b_r0 & 7) << 4);
    uint32_t bOff = (uint32_t)b_r0 * 128;

    float4 breg[6];
    const float4* wptr = (const float4*)(weight + wbase * EMBED_DIM);

    // prologue: B chunk 0 into regs, A chunk 0 via cp.async
    #pragma unroll
    for (int i = 0; i < 6; i++) {
        int idx = tid + 256 * i;
        breg[i] = wptr[(size_t)(idx >> 4) * 128 + (idx & 15)];
    }
    {
        const char* src = (const char*)g_embf + (size_t)tid * 16;
        uint32_t dst = sb + SM_A0 + tid * 16;
        #pragma unroll
        for (int i = 0; i < 8; i++) CP_ASYNC16(dst + i * 4096, src + i * 4096);
        CP_COMMIT();
    }

    for (int kc = 0; kc < NCHUNK; kc++) {
        int buf = kc & 1;
        uint32_t aBase = sb + (buf ? SM_A1 : SM_A0);
        uint32_t bBase = sb + (buf ? SM_B1 : SM_B0);

        CP_WAIT0();
        __syncthreads();   // A[kc] landed everywhere

        // convert prefetched B regs -> smem (swizzled) + sumsq
        {
            char* bdst = sm + (buf ? SM_B1 : SM_B0);
            #pragma unroll
            for (int i = 0; i < 6; i++) {
                int idx = tid + 256 * i;
                int row = idx >> 4;
                int f = idx & 15;
                float4 v = breg[i];
                float ss = v.x * v.x + v.y * v.y + v.z * v.z + v.w * v.w;
                __nv_bfloat162 p0 = __floats2bfloat162_rn(v.x, v.y);
                __nv_bfloat162 p1 = __floats2bfloat162_rn(v.z, v.w);
                uint2 u;
                u.x = *(uint32_t*)&p0;
                u.y = *(uint32_t*)&p1;
                uint32_t kb = (uint32_t)f * 8;
                *(uint2*)(bdst + row * 128 + (kb ^ ((row & 7) << 4))) = u;
                ss += __shfl_xor_sync(0xFFFFFFFFu, ss, 1);
                ss += __shfl_xor_sync(0xFFFFFFFFu, ss, 2);
                ss += __shfl_xor_sync(0xFFFFFFFFu, ss, 4);
                ss += __shfl_xor_sync(0xFFFFFFFFu, ss, 8);
                if ((tid & 15) == 0) rsum[row] += ss;
            }
        }

        // issue next A chunk cp.async into other buffer
        if (kc < NCHUNK - 1) {
            const char* src = (const char*)g_embf + (size_t)(kc + 1) * 32768 + (size_t)tid * 16;
            uint32_t dst = sb + (buf ? SM_A0 : SM_A1) + tid * 16;
            #pragma unroll
            for (int i = 0; i < 8; i++) CP_ASYNC16(dst + i * 4096, src + i * 4096);
            CP_COMMIT();
        }
        __syncthreads();   // B[kc] smem visible

        // issue next B LDGs (land during MMA)
        if (kc < NCHUNK - 1) {
            const float4* wp = (const float4*)(weight + wbase * EMBED_DIM + (kc + 1) * KCH);
            #pragma unroll
            for (int i = 0; i < 6; i++) {
                int idx = tid + 256 * i;
                breg[i] = wp[(size_t)(idx >> 4) * 128 + (idx & 15)];
            }
        }

        // MMA: 4 k-steps x (2 m-tiles x 12 n-tiles)
        uint32_t aRow0 = aBase + aOff;
        uint32_t aRow1 = aRow0 + 16 * 128;
        uint32_t bRow0 = bBase + bOff;
        #pragma unroll
        for (int ks = 0; ks < 4; ks++) {
            uint32_t kbA = ((uint32_t)(ks * 32) + a_hi16) ^ xrA;
            uint32_t kbB = ((uint32_t)(ks * 32) + b_k16) ^ xrB;
            uint32_t a0[4], a1[4], bfr[6][4];
            LDM_X4(a0, aRow0 + kbA);
            LDM_X4(a1, aRow1 + kbA);
            #pragma unroll
            for (int g = 0; g < 6; g++) LDM_X4(bfr[g], bRow0 + g * 2048 + kbB);
            #pragma unroll
            for (int nt = 0; nt < 12; nt++) {
                uint32_t b0 = bfr[nt >> 1][(nt & 1) * 2];
                uint32_t b1 = bfr[nt >> 1][(nt & 1) * 2 + 1];
                mma16816(acc[0][nt], a0, b0, b1);
                mma16816(acc[1][nt], a1, b0, b1);
            }
        }
    }
    __syncthreads();   // all ldmatrix reads done before cm overwrites buffers

    // finalize row rnorms
    if (tid < NT) rsum[tid] = 1.0f / fmaxf(sqrtf(rsum[tid]), 1e-12f);

    // dump accumulators to cm[256][97]
    float* cm = (float*)sm;
    int mrow = w * 32 + (lane >> 2);
    int mcol = (lane & 3) * 2;
    #pragma unroll
    for (int mt = 0; mt < 2; mt++) {
        #pragma unroll
        for (int nt = 0; nt < 12; nt++) {
            int m = mrow + mt * 16;
            int n = nt * 8 + mcol;
            cm[m * CM_STRIDE + n]           = acc[mt][nt][0];
            cm[m * CM_STRIDE + n + 1]       = acc[mt][nt][1];
            cm[(m + 8) * CM_STRIDE + n]     = acc[mt][nt][2];
            cm[(m + 8) * CM_STRIDE + n + 1] = acc[mt][nt][3];
        }
    }
    __syncthreads();

    // thread tid = sample tid: 32 classes, subcenter-max, exp-sum -> padded atomic
    float psum = 0.0f;
    const float* myrow = cm + tid * CM_STRIDE;
    #pragma unroll 8
    for (int c = 0; c < NT / 3; c++) {
        float c0 = myrow[3 * c + 0] * rsum[3 * c + 0];
        float c1 = myrow[3 * c + 1] * rsum[3 * c + 1];
        float c2 = myrow[3 * c + 2] * rsum[3 * c + 2];
        float m = fmaxf(c0, fmaxf(c1, c2));
        psum += __expf(SCALE * m - 64.0f);
    }
    atomicAdd(&g_sums[tid * SUMSTR], psum);   // 128B-strided: distinct L2 lines per sample
}

// ---------------- K3: margin correction + loss + mean ----------------
__global__ void k3_final(float* __restrict__ out) {
    int tid = threadIdx.x;   // 256, thread = sample
    float tot = g_sums[tid * SUMSTR];
    float cl = g_labcos[tid];
    float sine = sqrtf(fminf(fmaxf(1.0f - cl * cl, 0.0f), 1.0f));
    float phi = cl * COS_M - sine * SIN_M;
    phi = (cl > TH_) ? phi : (cl - MM_);
    float t2 = tot - __expf(SCALE * cl - 64.0f) + __expf(SCALE * phi - 64.0f);
    float loss = 64.0f + logf(t2) - SCALE * phi;

    __shared__ float red[256];
    red[tid] = loss;
    __syncthreads();
    for (int o = 128; o > 0; o >>= 1) { if (tid < o) red[tid] += red[tid + o]; __syncthreads(); }
    if (tid == 0) out[0] = red[0] * (1.0f / BATCH);
}

// ---------------- launch ----------------
extern "C" void kernel_launch(void* const* d_in, const int* in_sizes, int n_in,
                              void* d_out, int out_size) {
    const float* emb    = (const float*)d_in[0];
    const int*   labels = (const int*)d_in[1];     // int32 (JAX x64 disabled)
    const float* weight = (const float*)d_in[2];
    float* out = (float*)d_out;

    k1_norm_label<<<BATCH, 128>>>(emb, weight, labels);

    cudaFuncSetAttribute(k2_hmma, cudaFuncAttributeMaxDynamicSharedMemorySize, SMEM_REQ);
    k2_hmma<<<NCTA, 256, SMEM_REQ>>>(weight);

    k3_final<<<1, 256>>>(out);
}